// round 16
// baseline (speedup 1.0000x reference)
#include <cuda_runtime.h>
#include <cuda_fp16.h>
#include <cstdint>

#define Bb 2
#define Sq 2048
#define Dm 1024
#define Hh 16
#define Dk 64

// Scratch (allocation-free rule: __device__ globals) — f16 intermediates
__device__ __align__(16) __half g_qh[(size_t)Bb*Hh*Sq*Dk];
__device__ __align__(16) __half g_kh[(size_t)Bb*Hh*Sq*Dk];
__device__ __align__(16) __half g_vh[(size_t)Bb*Hh*Sq*Dk];
__device__ __align__(16) __half g_ao[(size_t)Bb*Sq*Dm];
__device__ __align__(16) __half g_eh[(size_t)Bb*Sq*Hh*Sq];      // unnormalized exp(s), fp16
__device__ __align__(16) uint32_t g_mbits[(size_t)Bb*Sq*(Sq/32)]; // packed mask bits

// ---------------------------------------------------------------------------
__device__ __forceinline__ uint32_t h2u(float a, float b) {
    __half2 h = __floats2half2_rn(a, b);
    return *(uint32_t*)&h;
}

__device__ __forceinline__ uint4 f8h(float4 a, float4 b) {
    uint4 r;
    r.x = h2u(a.x, a.y); r.y = h2u(a.z, a.w);
    r.z = h2u(b.x, b.y); r.w = h2u(b.z, b.w);
    return r;
}

__device__ __forceinline__ void mma_f16(float c[4],
    uint32_t a0, uint32_t a1, uint32_t a2, uint32_t a3,
    uint32_t b0, uint32_t b1)
{
    asm volatile(
        "mma.sync.aligned.m16n8k16.row.col.f32.f16.f16.f32 "
        "{%0,%1,%2,%3}, {%4,%5,%6,%7}, {%8,%9}, {%0,%1,%2,%3};"
        : "+f"(c[0]), "+f"(c[1]), "+f"(c[2]), "+f"(c[3])
        : "r"(a0), "r"(a1), "r"(a2), "r"(a3), "r"(b0), "r"(b1));
}

__device__ __forceinline__ void ldsm_x4(uint32_t& r0, uint32_t& r1,
                                        uint32_t& r2, uint32_t& r3, uint32_t addr)
{
    asm volatile("ldmatrix.sync.aligned.m8n8.x4.shared.b16 {%0,%1,%2,%3}, [%4];"
        : "=r"(r0), "=r"(r1), "=r"(r2), "=r"(r3) : "r"(addr));
}

__device__ __forceinline__ void ldsm_x4_t(uint32_t& r0, uint32_t& r1,
                                          uint32_t& r2, uint32_t& r3, uint32_t addr)
{
    asm volatile("ldmatrix.sync.aligned.m8n8.x4.trans.shared.b16 {%0,%1,%2,%3}, [%4];"
        : "=r"(r0), "=r"(r1), "=r"(r2), "=r"(r3) : "r"(addr));
}

__device__ __forceinline__ void cpa16(uint32_t saddr, const void* g) {
    asm volatile("cp.async.cg.shared.global [%0], [%1], 16;" :: "r"(saddr), "l"(g));
}
#define CP_COMMIT() asm volatile("cp.async.commit_group;")
#define CP_WAIT0()  asm volatile("cp.async.wait_group 0;")

__device__ __forceinline__ uint32_t s2u(const void* p) {
    return (uint32_t)__cvta_generic_to_shared(p);
}

// ============================================================================
// K0: pack mask ints -> bits.
// ============================================================================
__global__ __launch_bounds__(256) void pack_mask(const int* __restrict__ mask)
{
    size_t wdx = (size_t)blockIdx.x * 256 + threadIdx.x;
    const int4* p = (const int4*)(mask + wdx * 32);
    uint32_t bits = 0;
#pragma unroll
    for (int i = 0; i < 8; i++) {
        int4 v = p[i];
        bits |= (v.x != 0 ? 1u : 0u) << (i * 4 + 0);
        bits |= (v.y != 0 ? 1u : 0u) << (i * 4 + 1);
        bits |= (v.z != 0 ? 1u : 0u) << (i * 4 + 2);
        bits |= (v.w != 0 ? 1u : 0u) << (i * 4 + 3);
    }
    g_mbits[wdx] = bits;
}

// ============================================================================
// K1: fused Q/K/V projection, fp16 m16n8k16 (R11 proven).
// ============================================================================
__global__ __launch_bounds__(256) void proj_tc(
    const float* __restrict__ xq, const float* __restrict__ xk, const float* __restrict__ xv,
    const float* __restrict__ wq, const float* __restrict__ wk, const float* __restrict__ wv,
    const float* __restrict__ bq, const float* __restrict__ bk, const float* __restrict__ bv)
{
    const int which = blockIdx.z;
    const float* __restrict__ A    = which == 0 ? xq : (which == 1 ? xk : xv);
    const float* __restrict__ W    = which == 0 ? wq : (which == 1 ? wk : wv);
    const float* __restrict__ bias = which == 0 ? bq : (which == 1 ? bk : bv);
    __half* __restrict__ dst       = which == 0 ? g_qh : (which == 1 ? g_kh : g_vh);

    __shared__ __half As[2][128][24];
    __shared__ __half Bs[2][128][24];

    const int tid = threadIdx.x;
    const int lane = tid & 31, wid = tid >> 5;
    const int wm = wid & 1, wn = wid >> 1;
    const int bm = blockIdx.y * 128, bn = blockIdx.x * 128;
    const int lr = lane >> 2, lc = lane & 3;

    const int row0 = tid >> 1, seg = (tid & 1) * 8;

    const int a_row = lane & 15;
    const int a_cB  = ((lane >> 4) & 1) * 16;
    const int b_row = (lane & 7) + ((lane >> 3) & 1) * 8;
    const int b_cB  = ((lane >> 4) & 1) * 16;

    const uint32_t sA = s2u(&As[0][0][0]);
    const uint32_t sB = s2u(&Bs[0][0][0]);

    float4 ra0, ra1, rb0, rb1;

#define PJ_LD(k0) do { \
    ra0 = *(const float4*)(A + (size_t)(bm + row0) * Dm + (k0) + seg); \
    ra1 = *(const float4*)(A + (size_t)(bm + row0) * Dm + (k0) + seg + 4); \
    rb0 = *(const float4*)(W + (size_t)(bn + row0) * Dm + (k0) + seg); \
    rb1 = *(const float4*)(W + (size_t)(bn + row0) * Dm + (k0) + seg + 4); \
} while (0)

#define PJ_ST(st) do { \
    *(uint4*)&As[st][row0][seg] = f8h(ra0, ra1); \
    *(uint4*)&Bs[st][row0][seg] = f8h(rb0, rb1); \
} while (0)

    float acc[4][4][4];
#pragma unroll
    for (int i = 0; i < 4; i++)
#pragma unroll
        for (int j = 0; j < 4; j++)
#pragma unroll
            for (int t = 0; t < 4; t++) acc[i][j][t] = 0.f;

    PJ_LD(0); PJ_ST(0); __syncthreads();

    for (int it = 0; it < 64; it++) {
        const int cur = it & 1;
        if (it < 63) PJ_LD((it + 1) * 16);

        uint32_t af[4][4], bf[4][2];
#pragma unroll
        for (int mt = 0; mt < 4; mt++)
            ldsm_x4(af[mt][0], af[mt][1], af[mt][2], af[mt][3],
                sA + (cur * 128 + wm * 64 + mt * 16 + a_row) * 48 + a_cB);
#pragma unroll
        for (int ntp = 0; ntp < 2; ntp++) {
            uint32_t r0, r1, r2, r3;
            ldsm_x4(r0, r1, r2, r3,
                sB + (cur * 128 + wn * 32 + ntp * 16 + b_row) * 48 + b_cB);
            bf[2 * ntp][0] = r0; bf[2 * ntp][1] = r2;
            bf[2 * ntp + 1][0] = r1; bf[2 * ntp + 1][1] = r3;
        }
#pragma unroll
        for (int mt = 0; mt < 4; mt++)
#pragma unroll
            for (int nt = 0; nt < 4; nt++)
                mma_f16(acc[mt][nt], af[mt][0], af[mt][1], af[mt][2], af[mt][3],
                        bf[nt][0], bf[nt][1]);

        if (it < 63) PJ_ST(cur ^ 1);
        __syncthreads();
    }

#pragma unroll
    for (int mt = 0; mt < 4; mt++) {
#pragma unroll
        for (int nt = 0; nt < 4; nt++) {
            int col = bn + wn * 32 + nt * 8 + lc * 2;
            int h = col >> 6, d = col & 63;
            float b0 = bias[col], b1 = bias[col + 1];
#pragma unroll
            for (int half = 0; half < 2; half++) {
                int m = bm + wm * 64 + mt * 16 + lr + half * 8;
                int b = m >> 11;
                int s = m & (Sq - 1);
                __half2 hv = __floats2half2_rn(acc[mt][nt][half * 2 + 0] + b0,
                                               acc[mt][nt][half * 2 + 1] + b1);
                *(__half2*)(dst + (((size_t)(b * Hh + h) * Sq + s) << 6) + d) = hv;
            }
        }
    }
#undef PJ_LD
#undef PJ_ST
}

// ============================================================================
// K2: fused attention (R14 proven) + in-kernel normalization tail.
// Each block normalizes its own 256 rows after computing inv (E region is
// freshly written -> partial L2 hits; no extra kernel launch).
// ============================================================================
#define QT 256

__global__ __launch_bounds__(512, 1) void attn_fused(float* __restrict__ sc)
{
    extern __shared__ char shb[];
    __half (*Qs)[72]     = (__half(*)[72])shb;
    __half (*Ks)[64][72] = (__half(*)[64][72])(shb + 36864);
    __half (*Vs)[64][72] = (__half(*)[64][72])(shb + 55296);
    __half (*Ps)[72]     = (__half(*)[72])(shb + 73728);
    float  *sInv         = (float*)(shb + 73728);               // reused after loop

    const int bh = blockIdx.y;
    const int b = bh >> 4, h = bh & 15;
    const int q0 = blockIdx.x * QT;
    const __half* qp    = g_qh + ((size_t)bh * Sq + q0) * Dk;
    const __half* kbase = g_kh + (size_t)bh * Sq * Dk;
    const __half* vbase = g_vh + (size_t)bh * Sq * Dk;

    const int tid = threadIdx.x;
    const int lane = tid & 31, w = tid >> 5;
    const int lr = lane >> 2, lc = lane & 3;
    const int r0 = 16 * w + lr;
    const int qg0 = q0 + r0;

    const int a_row = lane & 15;
    const int a_cB  = ((lane >> 4) & 1) * 16;
    const int b_row = (lane & 7) + ((lane >> 3) & 1) * 8;
    const int b_cB  = ((lane >> 4) & 1) * 16;

    const uint32_t sQ = s2u(&Qs[0][0]);
    const uint32_t sK = s2u(&Ks[0][0][0]);
    const uint32_t sV = s2u(&Vs[0][0][0]);

    const int rA = tid >> 3, segA = (tid & 7) * 8;

#define AT_CPKV(st, kt) do { \
    cpa16(sK + ((st) * 64 + rA) * 144 + segA * 2, kbase + (size_t)((kt) + rA) * Dk + segA); \
    cpa16(sV + ((st) * 64 + rA) * 144 + segA * 2, vbase + (size_t)((kt) + rA) * Dk + segA); \
} while (0)

#pragma unroll
    for (int t = 0; t < 4; t++) {
        int f = tid + t * 512;
        int row = f >> 3, sg = (f & 7) * 8;
        cpa16(sQ + row * 144 + sg * 2, qp + row * Dk + sg);
    }
    AT_CPKV(0, 0);
    CP_COMMIT();
    CP_WAIT0();
    __syncthreads();

    uint32_t qfr[4][4];
#pragma unroll
    for (int g = 0; g < 4; g++)
        ldsm_x4(qfr[g][0], qfr[g][1], qfr[g][2], qfr[g][3],
            sQ + (16 * w + a_row) * 144 + g * 32 + a_cB);

    const uint32_t* mb0 = g_mbits + ((size_t)(b * Sq + qg0)) * 64;
    const uint32_t* mb1 = mb0 + 8 * 64;

    float lsum0 = 0.f, lsum1 = 0.f;
    float o_acc[8][4];
#pragma unroll
    for (int nt = 0; nt < 8; nt++)
#pragma unroll
        for (int e = 0; e < 4; e++) o_acc[nt][e] = 0.f;

    for (int it = 0; it < Sq / 64; it++) {
        const int cur = it & 1;
        const int kt = it * 64;
        if (it < Sq / 64 - 1) { AT_CPKV(cur ^ 1, kt + 64); CP_COMMIT(); }

        float acc[8][4];
#pragma unroll
        for (int nt = 0; nt < 8; nt++)
#pragma unroll
            for (int e = 0; e < 4; e++) acc[nt][e] = 0.f;

        // ---- QK^T ----
#pragma unroll
        for (int g = 0; g < 4; g++) {
            uint32_t kb[8][2];
#pragma unroll
            for (int ntp = 0; ntp < 4; ntp++) {
                uint32_t r0u, r1u, r2u, r3u;
                ldsm_x4(r0u, r1u, r2u, r3u,
                    sK + (cur * 64 + ntp * 16 + b_row) * 144 + g * 32 + b_cB);
                kb[2 * ntp][0] = r0u; kb[2 * ntp][1] = r2u;
                kb[2 * ntp + 1][0] = r1u; kb[2 * ntp + 1][1] = r3u;
            }
#pragma unroll
            for (int nt = 0; nt < 8; nt++)
                mma_f16(acc[nt], qfr[g][0], qfr[g][1], qfr[g][2], qfr[g][3],
                        kb[nt][0], kb[nt][1]);
        }

        // ---- mask bits, exp, row sums; stage fp16 into Ps ----
        uint2 mw0 = *(const uint2*)(mb0 + (kt >> 5));
        uint2 mw1 = *(const uint2*)(mb1 + (kt >> 5));
#pragma unroll
        for (int nt = 0; nt < 8; nt++) {
            const int p = nt * 8 + lc * 2;
            const uint32_t s0 = ((nt < 4) ? mw0.x : mw0.y) >> (p & 31);
            const uint32_t s1 = ((nt < 4) ? mw1.x : mw1.y) >> (p & 31);
            float e00 = (s0 & 1u) ? __expf(acc[nt][0] * 0.125f) : 0.f;
            float e01 = (s0 & 2u) ? __expf(acc[nt][1] * 0.125f) : 0.f;
            float e10 = (s1 & 1u) ? __expf(acc[nt][2] * 0.125f) : 0.f;
            float e11 = (s1 & 2u) ? __expf(acc[nt][3] * 0.125f) : 0.f;
            lsum0 += e00 + e01;
            lsum1 += e10 + e11;
            acc[nt][0] = e00; acc[nt][1] = e01;
            acc[nt][2] = e10; acc[nt][3] = e11;
            int cl = nt * 8 + lc * 2;
            *(__half2*)&Ps[r0][cl]     = __floats2half2_rn(e00, e01);
            *(__half2*)&Ps[r0 + 8][cl] = __floats2half2_rn(e10, e11);
        }

        // ---- O += E @ V (register A frags; doesn't touch Ps) ----
#pragma unroll
        for (int g = 0; g < 4; g++) {
            uint32_t a0 = h2u(acc[2 * g][0],     acc[2 * g][1]);
            uint32_t a1 = h2u(acc[2 * g][2],     acc[2 * g][3]);
            uint32_t a2 = h2u(acc[2 * g + 1][0], acc[2 * g + 1][1]);
            uint32_t a3 = h2u(acc[2 * g + 1][2], acc[2 * g + 1][3]);
            uint32_t vb[8][2];
#pragma unroll
            for (int ntp = 0; ntp < 4; ntp++) {
                uint32_t r0u, r1u, r2u, r3u;
                ldsm_x4_t(r0u, r1u, r2u, r3u,
                    sV + (cur * 64 + g * 16 + b_row) * 144 + ntp * 32 + b_cB);
                vb[2 * ntp][0] = r0u; vb[2 * ntp][1] = r1u;
                vb[2 * ntp + 1][0] = r2u; vb[2 * ntp + 1][1] = r3u;
            }
#pragma unroll
            for (int nt = 0; nt < 8; nt++)
                mma_f16(o_acc[nt], a0, a1, a2, a3, vb[nt][0], vb[nt][1]);
        }
        __syncthreads();   // Ps fully written

        // coalesced write of unnormalized E tile (fp16)
#pragma unroll
        for (int t = 0; t < 4; t++) {
            int f = tid + t * 512;
            int row = f >> 3;
            int sg = (f & 7) * 8;
            uint4 v = *(const uint4*)&Ps[row][sg];
            *(uint4*)(g_eh + (((size_t)(b * Sq + q0 + row)) * Hh + h) * Sq + kt + sg) = v;
        }

        if (it < Sq / 64 - 1) CP_WAIT0();
        __syncthreads();   // Ps reads done; next tile may overwrite
    }

    // reduce row sums over the 4 lc lanes
    lsum0 += __shfl_xor_sync(0xffffffffu, lsum0, 1);
    lsum0 += __shfl_xor_sync(0xffffffffu, lsum0, 2);
    lsum1 += __shfl_xor_sync(0xffffffffu, lsum1, 1);
    lsum1 += __shfl_xor_sync(0xffffffffu, lsum1, 2);
    const float inv0 = 1.0f / lsum0, inv1 = 1.0f / lsum1;

    // epilogue: write O (scaled, f16) to g_ao
    __half* orow0 = g_ao + (size_t)(b * Sq + qg0) * Dm + h * Dk;
    __half* orow1 = orow0 + 8 * Dm;
#pragma unroll
    for (int nt = 0; nt < 8; nt++) {
        int d = nt * 8 + lc * 2;
        *(__half2*)(orow0 + d) = __floats2half2_rn(o_acc[nt][0] * inv0, o_acc[nt][1] * inv0);
        *(__half2*)(orow1 + d) = __floats2half2_rn(o_acc[nt][2] * inv1, o_acc[nt][3] * inv1);
    }

    // ---- normalization tail: this block's 256 rows of scores ----
    __syncthreads();                 // Ps no longer needed; reuse as sInv
    if (lc == 0) {
        sInv[r0]     = inv0;
        sInv[r0 + 8] = inv1;
    }
    __syncthreads();

    for (int row = 0; row < QT; row++) {
        const float s = sInv[row];
        const size_t ridx = ((size_t)(b * Sq + q0 + row)) * Hh + h;
        const __half* ep = g_eh + ridx * Sq;
        float* op = sc + ridx * Sq;
        // 2048 floats = 512 f4 slots; 512 threads, 1 each
        uint2 u = ((const uint2*)ep)[tid];
        __half2 h0 = *(__half2*)&u.x;
        __half2 h1 = *(__half2*)&u.y;
        float2 f0 = __half22float2(h0);
        float2 f1 = __half22float2(h1);
        float4 v;
        v.x = f0.x * s; v.y = f0.y * s;
        v.z = f1.x * s; v.w = f1.y * s;
        ((float4*)op)[tid] = v;
    }
#undef AT_CPKV
}

// ============================================================================
// K4: final projection out = g_ao(f16) @ Wo^T + bo  (R14 proven)
// ============================================================================
__global__ __launch_bounds__(256) void outproj_tc(
    const float* __restrict__ W, const float* __restrict__ bias, float* __restrict__ C)
{
    __shared__ __half As[2][128][24];
    __shared__ __half Bs[2][128][24];
    const int tid = threadIdx.x;
    const int lane = tid & 31, wid = tid >> 5;
    const int wm = wid & 1, wn = wid >> 1;
    const int bm = blockIdx.y * 128, bn = blockIdx.x * 128;
    const int lr = lane >> 2, lc = lane & 3;
    const __half* __restrict__ A = g_ao;

    const int row0 = tid >> 1, seg = (tid & 1) * 8;

    const int a_row = lane & 15;
    const int a_cB  = ((lane >> 4) & 1) * 16;
    const int b_row = (lane & 7) + ((lane >> 3) & 1) * 8;
    const int b_cB  = ((lane >> 4) & 1) * 16;

    const uint32_t sA = s2u(&As[0][0][0]);
    const uint32_t sB = s2u(&Bs[0][0][0]);

    float4 rb0, rb1;

#define OP_CPA(st, k0) \
    cpa16(sA + ((st) * 128 + row0) * 48 + seg * 2, A + (size_t)(bm + row0) * Dm + (k0) + seg)

#define OP_LDB(k0) do { \
    rb0 = *(const float4*)(W + (size_t)(bn + row0) * Dm + (k0) + seg); \
    rb1 = *(const float4*)(W + (size_t)(bn + row0) * Dm + (k0) + seg + 4); \
} while (0)

#define OP_STB(st) do { \
    *(uint4*)&Bs[st][row0][seg] = f8h(rb0, rb1); \
} while (0)

    float acc[4][4][4];
#pragma unroll
    for (int i = 0; i < 4; i++)
#pragma unroll
        for (int j = 0; j < 4; j++)
#pragma unroll
            for (int t = 0; t < 4; t++) acc[i][j][t] = 0.f;

    OP_CPA(0, 0); CP_COMMIT(); OP_LDB(0); OP_STB(0); CP_WAIT0(); __syncthreads();

    for (int it = 0; it < 64; it++) {
        const int cur = it & 1;
        if (it < 63) { OP_CPA(cur ^ 1, (it + 1) * 16); CP_COMMIT(); OP_LDB((it + 1) * 16); }

        uint32_t af[4][4], bf[4][2];
#pragma unroll
        for (int mt = 0; mt < 4; mt++)
            ldsm_x4(af[mt][0], af[mt][1], af[mt][2], af[mt][3],
                sA + (cur * 128 + wm * 64 + mt * 16 + a_row) * 48 + a_cB);
#pragma unroll
        for (int ntp = 0; ntp < 2; ntp++) {
            uint32_t r0, r1, r2, r3;
            ldsm_x4(r0, r1, r2, r3,
                sB + (cur * 128 + wn * 32 + ntp * 16 + b_row) * 48 + b_cB);
            bf[2 * ntp][0] = r0; bf[2 * ntp][1] = r2;
            bf[2 * ntp + 1][0] = r1; bf[2 * ntp + 1][1] = r3;
        }
#pragma unroll
        for (int mt = 0; mt < 4; mt++)
#pragma unroll
            for (int nt = 0; nt < 4; nt++)
                mma_f16(acc[mt][nt], af[mt][0], af[mt][1], af[mt][2], af[mt][3],
                        bf[nt][0], bf[nt][1]);

        if (it < 63) { OP_STB(cur ^ 1); CP_WAIT0(); }
        __syncthreads();
    }

#pragma unroll
    for (int mt = 0; mt < 4; mt++) {
#pragma unroll
        for (int nt = 0; nt < 4; nt++) {
            int col = bn + wn * 32 + nt * 8 + lc * 2;
            float b0 = bias[col], b1 = bias[col + 1];
#pragma unroll
            for (int half = 0; half < 2; half++) {
                int m = bm + wm * 64 + mt * 16 + lr + half * 8;
                float2 v;
                v.x = acc[mt][nt][half * 2 + 0] + b0;
                v.y = acc[mt][nt][half * 2 + 1] + b1;
                *(float2*)(C + (size_t)m * Dm + col) = v;
            }
        }
    }
#undef OP_CPA
#undef OP_LDB
#undef OP_STB
}

// ============================================================================
extern "C" void kernel_launch(void* const* d_in, const int* in_sizes, int n_in,
                              void* d_out, int out_size)
{
    const float* q    = (const float*)d_in[0];
    const float* k    = (const float*)d_in[1];
    const float* v    = (const float*)d_in[2];
    const int*   mask = (const int*)d_in[3];
    const float* Wq   = (const float*)d_in[4];
    const float* bq   = (const float*)d_in[5];
    const float* Wk   = (const float*)d_in[6];
    const float* bk   = (const float*)d_in[7];
    const float* Wv   = (const float*)d_in[8];
    const float* bv   = (const float*)d_in[9];
    const float* Wo   = (const float*)d_in[10];
    const float* bo   = (const float*)d_in[11];

    float* out = (float*)d_out;
    float* sc  = out + (size_t)Bb * Sq * Dm;   // scores_out region

    const int attn_smem = 110592;
    cudaFuncSetAttribute(attn_fused, cudaFuncAttributeMaxDynamicSharedMemorySize, attn_smem);

    pack_mask<<<(Bb * Sq * (Sq / 32)) / 256, 256>>>(mask);

    dim3 gp(Dm / 128, (Bb * Sq) / 128, 3);
    proj_tc<<<gp, 256>>>(q, k, v, Wq, Wk, Wv, bq, bk, bv);

    dim3 ga(Sq / QT, Bb * Hh);
    attn_fused<<<ga, 512, attn_smem>>>(sc);

    dim3 go(Dm / 128, (Bb * Sq) / 128);
    outproj_tc<<<go, 256>>>(Wo, bo, out);
}

// round 17
// speedup vs baseline: 1.2503x; 1.2503x over previous
#include <cuda_runtime.h>
#include <cuda_fp16.h>
#include <cstdint>

#define Bb 2
#define Sq 2048
#define Dm 1024
#define Hh 16
#define Dk 64

// Scratch (allocation-free rule: __device__ globals) — f16 intermediates
__device__ __align__(16) __half g_qh[(size_t)Bb*Hh*Sq*Dk];
__device__ __align__(16) __half g_kh[(size_t)Bb*Hh*Sq*Dk];
__device__ __align__(16) __half g_vh[(size_t)Bb*Hh*Sq*Dk];
__device__ __align__(16) __half g_ao[(size_t)Bb*Sq*Dm];
__device__ __align__(16) float  g_linv[(size_t)Bb*Sq*Hh];
__device__ __align__(16) __half g_eh[(size_t)Bb*Sq*Hh*Sq];      // unnormalized exp(s), fp16
__device__ __align__(16) uint32_t g_mbits[(size_t)Bb*Sq*(Sq/32)]; // packed mask bits

// ---------------------------------------------------------------------------
__device__ __forceinline__ uint32_t h2u(float a, float b) {
    __half2 h = __floats2half2_rn(a, b);
    return *(uint32_t*)&h;
}

__device__ __forceinline__ uint4 f8h(float4 a, float4 b) {
    uint4 r;
    r.x = h2u(a.x, a.y); r.y = h2u(a.z, a.w);
    r.z = h2u(b.x, b.y); r.w = h2u(b.z, b.w);
    return r;
}

__device__ __forceinline__ void mma_f16(float c[4],
    uint32_t a0, uint32_t a1, uint32_t a2, uint32_t a3,
    uint32_t b0, uint32_t b1)
{
    asm volatile(
        "mma.sync.aligned.m16n8k16.row.col.f32.f16.f16.f32 "
        "{%0,%1,%2,%3}, {%4,%5,%6,%7}, {%8,%9}, {%0,%1,%2,%3};"
        : "+f"(c[0]), "+f"(c[1]), "+f"(c[2]), "+f"(c[3])
        : "r"(a0), "r"(a1), "r"(a2), "r"(a3), "r"(b0), "r"(b1));
}

__device__ __forceinline__ void ldsm_x4(uint32_t& r0, uint32_t& r1,
                                        uint32_t& r2, uint32_t& r3, uint32_t addr)
{
    asm volatile("ldmatrix.sync.aligned.m8n8.x4.shared.b16 {%0,%1,%2,%3}, [%4];"
        : "=r"(r0), "=r"(r1), "=r"(r2), "=r"(r3) : "r"(addr));
}

__device__ __forceinline__ void ldsm_x4_t(uint32_t& r0, uint32_t& r1,
                                          uint32_t& r2, uint32_t& r3, uint32_t addr)
{
    asm volatile("ldmatrix.sync.aligned.m8n8.x4.trans.shared.b16 {%0,%1,%2,%3}, [%4];"
        : "=r"(r0), "=r"(r1), "=r"(r2), "=r"(r3) : "r"(addr));
}

__device__ __forceinline__ void cpa16(uint32_t saddr, const void* g) {
    asm volatile("cp.async.cg.shared.global [%0], [%1], 16;" :: "r"(saddr), "l"(g));
}
#define CP_COMMIT() asm volatile("cp.async.commit_group;")
#define CP_WAIT0()  asm volatile("cp.async.wait_group 0;")

__device__ __forceinline__ uint32_t s2u(const void* p) {
    return (uint32_t)__cvta_generic_to_shared(p);
}

// ============================================================================
// K0: pack mask ints -> bits.
// ============================================================================
__global__ __launch_bounds__(256) void pack_mask(const int* __restrict__ mask)
{
    size_t wdx = (size_t)blockIdx.x * 256 + threadIdx.x;
    const int4* p = (const int4*)(mask + wdx * 32);
    uint32_t bits = 0;
#pragma unroll
    for (int i = 0; i < 8; i++) {
        int4 v = p[i];
        bits |= (v.x != 0 ? 1u : 0u) << (i * 4 + 0);
        bits |= (v.y != 0 ? 1u : 0u) << (i * 4 + 1);
        bits |= (v.z != 0 ? 1u : 0u) << (i * 4 + 2);
        bits |= (v.w != 0 ? 1u : 0u) << (i * 4 + 3);
    }
    g_mbits[wdx] = bits;
}

// ============================================================================
// K1: fused Q/K/V projection, fp16 m16n8k16 (R11 proven).
// ============================================================================
__global__ __launch_bounds__(256) void proj_tc(
    const float* __restrict__ xq, const float* __restrict__ xk, const float* __restrict__ xv,
    const float* __restrict__ wq, const float* __restrict__ wk, const float* __restrict__ wv,
    const float* __restrict__ bq, const float* __restrict__ bk, const float* __restrict__ bv)
{
    const int which = blockIdx.z;
    const float* __restrict__ A    = which == 0 ? xq : (which == 1 ? xk : xv);
    const float* __restrict__ W    = which == 0 ? wq : (which == 1 ? wk : wv);
    const float* __restrict__ bias = which == 0 ? bq : (which == 1 ? bk : bv);
    __half* __restrict__ dst       = which == 0 ? g_qh : (which == 1 ? g_kh : g_vh);

    __shared__ __half As[2][128][24];
    __shared__ __half Bs[2][128][24];

    const int tid = threadIdx.x;
    const int lane = tid & 31, wid = tid >> 5;
    const int wm = wid & 1, wn = wid >> 1;
    const int bm = blockIdx.y * 128, bn = blockIdx.x * 128;
    const int lr = lane >> 2, lc = lane & 3;

    const int row0 = tid >> 1, seg = (tid & 1) * 8;

    const int a_row = lane & 15;
    const int a_cB  = ((lane >> 4) & 1) * 16;
    const int b_row = (lane & 7) + ((lane >> 3) & 1) * 8;
    const int b_cB  = ((lane >> 4) & 1) * 16;

    const uint32_t sA = s2u(&As[0][0][0]);
    const uint32_t sB = s2u(&Bs[0][0][0]);

    float4 ra0, ra1, rb0, rb1;

#define PJ_LD(k0) do { \
    ra0 = *(const float4*)(A + (size_t)(bm + row0) * Dm + (k0) + seg); \
    ra1 = *(const float4*)(A + (size_t)(bm + row0) * Dm + (k0) + seg + 4); \
    rb0 = *(const float4*)(W + (size_t)(bn + row0) * Dm + (k0) + seg); \
    rb1 = *(const float4*)(W + (size_t)(bn + row0) * Dm + (k0) + seg + 4); \
} while (0)

#define PJ_ST(st) do { \
    *(uint4*)&As[st][row0][seg] = f8h(ra0, ra1); \
    *(uint4*)&Bs[st][row0][seg] = f8h(rb0, rb1); \
} while (0)

    float acc[4][4][4];
#pragma unroll
    for (int i = 0; i < 4; i++)
#pragma unroll
        for (int j = 0; j < 4; j++)
#pragma unroll
            for (int t = 0; t < 4; t++) acc[i][j][t] = 0.f;

    PJ_LD(0); PJ_ST(0); __syncthreads();

    for (int it = 0; it < 64; it++) {
        const int cur = it & 1;
        if (it < 63) PJ_LD((it + 1) * 16);

        uint32_t af[4][4], bf[4][2];
#pragma unroll
        for (int mt = 0; mt < 4; mt++)
            ldsm_x4(af[mt][0], af[mt][1], af[mt][2], af[mt][3],
                sA + (cur * 128 + wm * 64 + mt * 16 + a_row) * 48 + a_cB);
#pragma unroll
        for (int ntp = 0; ntp < 2; ntp++) {
            uint32_t r0, r1, r2, r3;
            ldsm_x4(r0, r1, r2, r3,
                sB + (cur * 128 + wn * 32 + ntp * 16 + b_row) * 48 + b_cB);
            bf[2 * ntp][0] = r0; bf[2 * ntp][1] = r2;
            bf[2 * ntp + 1][0] = r1; bf[2 * ntp + 1][1] = r3;
        }
#pragma unroll
        for (int mt = 0; mt < 4; mt++)
#pragma unroll
            for (int nt = 0; nt < 4; nt++)
                mma_f16(acc[mt][nt], af[mt][0], af[mt][1], af[mt][2], af[mt][3],
                        bf[nt][0], bf[nt][1]);

        if (it < 63) PJ_ST(cur ^ 1);
        __syncthreads();
    }

#pragma unroll
    for (int mt = 0; mt < 4; mt++) {
#pragma unroll
        for (int nt = 0; nt < 4; nt++) {
            int col = bn + wn * 32 + nt * 8 + lc * 2;
            int h = col >> 6, d = col & 63;
            float b0 = bias[col], b1 = bias[col + 1];
#pragma unroll
            for (int half = 0; half < 2; half++) {
                int m = bm + wm * 64 + mt * 16 + lr + half * 8;
                int b = m >> 11;
                int s = m & (Sq - 1);
                __half2 hv = __floats2half2_rn(acc[mt][nt][half * 2 + 0] + b0,
                                               acc[mt][nt][half * 2 + 1] + b1);
                *(__half2*)(dst + (((size_t)(b * Hh + h) * Sq + s) << 6) + d) = hv;
            }
        }
    }
#undef PJ_LD
#undef PJ_ST
}

// ============================================================================
// K2: fused attention (R14 proven).
// ============================================================================
#define QT 256

__global__ __launch_bounds__(512, 1) void attn_fused()
{
    extern __shared__ char shb[];
    __half (*Qs)[72]     = (__half(*)[72])shb;
    __half (*Ks)[64][72] = (__half(*)[64][72])(shb + 36864);
    __half (*Vs)[64][72] = (__half(*)[64][72])(shb + 55296);
    __half (*Ps)[72]     = (__half(*)[72])(shb + 73728);

    const int bh = blockIdx.y;
    const int b = bh >> 4, h = bh & 15;
    const int q0 = blockIdx.x * QT;
    const __half* qp    = g_qh + ((size_t)bh * Sq + q0) * Dk;
    const __half* kbase = g_kh + (size_t)bh * Sq * Dk;
    const __half* vbase = g_vh + (size_t)bh * Sq * Dk;

    const int tid = threadIdx.x;
    const int lane = tid & 31, w = tid >> 5;
    const int lr = lane >> 2, lc = lane & 3;
    const int r0 = 16 * w + lr;
    const int qg0 = q0 + r0;

    const int a_row = lane & 15;
    const int a_cB  = ((lane >> 4) & 1) * 16;
    const int b_row = (lane & 7) + ((lane >> 3) & 1) * 8;
    const int b_cB  = ((lane >> 4) & 1) * 16;

    const uint32_t sQ = s2u(&Qs[0][0]);
    const uint32_t sK = s2u(&Ks[0][0][0]);
    const uint32_t sV = s2u(&Vs[0][0][0]);

    const int rA = tid >> 3, segA = (tid & 7) * 8;

#define AT_CPKV(st, kt) do { \
    cpa16(sK + ((st) * 64 + rA) * 144 + segA * 2, kbase + (size_t)((kt) + rA) * Dk + segA); \
    cpa16(sV + ((st) * 64 + rA) * 144 + segA * 2, vbase + (size_t)((kt) + rA) * Dk + segA); \
} while (0)

#pragma unroll
    for (int t = 0; t < 4; t++) {
        int f = tid + t * 512;
        int row = f >> 3, sg = (f & 7) * 8;
        cpa16(sQ + row * 144 + sg * 2, qp + row * Dk + sg);
    }
    AT_CPKV(0, 0);
    CP_COMMIT();
    CP_WAIT0();
    __syncthreads();

    uint32_t qfr[4][4];
#pragma unroll
    for (int g = 0; g < 4; g++)
        ldsm_x4(qfr[g][0], qfr[g][1], qfr[g][2], qfr[g][3],
            sQ + (16 * w + a_row) * 144 + g * 32 + a_cB);

    const uint32_t* mb0 = g_mbits + ((size_t)(b * Sq + qg0)) * 64;
    const uint32_t* mb1 = mb0 + 8 * 64;

    float lsum0 = 0.f, lsum1 = 0.f;
    float o_acc[8][4];
#pragma unroll
    for (int nt = 0; nt < 8; nt++)
#pragma unroll
        for (int e = 0; e < 4; e++) o_acc[nt][e] = 0.f;

    for (int it = 0; it < Sq / 64; it++) {
        const int cur = it & 1;
        const int kt = it * 64;
        if (it < Sq / 64 - 1) { AT_CPKV(cur ^ 1, kt + 64); CP_COMMIT(); }

        float acc[8][4];
#pragma unroll
        for (int nt = 0; nt < 8; nt++)
#pragma unroll
            for (int e = 0; e < 4; e++) acc[nt][e] = 0.f;

#pragma unroll
        for (int g = 0; g < 4; g++) {
            uint32_t kb[8][2];
#pragma unroll
            for (int ntp = 0; ntp < 4; ntp++) {
                uint32_t r0u, r1u, r2u, r3u;
                ldsm_x4(r0u, r1u, r2u, r3u,
                    sK + (cur * 64 + ntp * 16 + b_row) * 144 + g * 32 + b_cB);
                kb[2 * ntp][0] = r0u; kb[2 * ntp][1] = r2u;
                kb[2 * ntp + 1][0] = r1u; kb[2 * ntp + 1][1] = r3u;
            }
#pragma unroll
            for (int nt = 0; nt < 8; nt++)
                mma_f16(acc[nt], qfr[g][0], qfr[g][1], qfr[g][2], qfr[g][3],
                        kb[nt][0], kb[nt][1]);
        }

        uint2 mw0 = *(const uint2*)(mb0 + (kt >> 5));
        uint2 mw1 = *(const uint2*)(mb1 + (kt >> 5));
#pragma unroll
        for (int nt = 0; nt < 8; nt++) {
            const int p = nt * 8 + lc * 2;
            const uint32_t s0 = ((nt < 4) ? mw0.x : mw0.y) >> (p & 31);
            const uint32_t s1 = ((nt < 4) ? mw1.x : mw1.y) >> (p & 31);
            float e00 = (s0 & 1u) ? __expf(acc[nt][0] * 0.125f) : 0.f;
            float e01 = (s0 & 2u) ? __expf(acc[nt][1] * 0.125f) : 0.f;
            float e10 = (s1 & 1u) ? __expf(acc[nt][2] * 0.125f) : 0.f;
            float e11 = (s1 & 2u) ? __expf(acc[nt][3] * 0.125f) : 0.f;
            lsum0 += e00 + e01;
            lsum1 += e10 + e11;
            acc[nt][0] = e00; acc[nt][1] = e01;
            acc[nt][2] = e10; acc[nt][3] = e11;
            int cl = nt * 8 + lc * 2;
            *(__half2*)&Ps[r0][cl]     = __floats2half2_rn(e00, e01);
            *(__half2*)&Ps[r0 + 8][cl] = __floats2half2_rn(e10, e11);
        }
        __syncthreads();

#pragma unroll
        for (int t = 0; t < 4; t++) {
            int f = tid + t * 512;
            int row = f >> 3;
            int sg = (f & 7) * 8;
            uint4 v = *(const uint4*)&Ps[row][sg];
            *(uint4*)(g_eh + (((size_t)(b * Sq + q0 + row)) * Hh + h) * Sq + kt + sg) = v;
        }

#pragma unroll
        for (int g = 0; g < 4; g++) {
            uint32_t a0 = h2u(acc[2 * g][0],     acc[2 * g][1]);
            uint32_t a1 = h2u(acc[2 * g][2],     acc[2 * g][3]);
            uint32_t a2 = h2u(acc[2 * g + 1][0], acc[2 * g + 1][1]);
            uint32_t a3 = h2u(acc[2 * g + 1][2], acc[2 * g + 1][3]);
            uint32_t vb[8][2];
#pragma unroll
            for (int ntp = 0; ntp < 4; ntp++) {
                uint32_t r0u, r1u, r2u, r3u;
                ldsm_x4_t(r0u, r1u, r2u, r3u,
                    sV + (cur * 64 + g * 16 + b_row) * 144 + ntp * 32 + b_cB);
                vb[2 * ntp][0] = r0u; vb[2 * ntp][1] = r1u;
                vb[2 * ntp + 1][0] = r2u; vb[2 * ntp + 1][1] = r3u;
            }
#pragma unroll
            for (int nt = 0; nt < 8; nt++)
                mma_f16(o_acc[nt], a0, a1, a2, a3, vb[nt][0], vb[nt][1]);
        }

        if (it < Sq / 64 - 1) CP_WAIT0();
        __syncthreads();
    }

    lsum0 += __shfl_xor_sync(0xffffffffu, lsum0, 1);
    lsum0 += __shfl_xor_sync(0xffffffffu, lsum0, 2);
    lsum1 += __shfl_xor_sync(0xffffffffu, lsum1, 1);
    lsum1 += __shfl_xor_sync(0xffffffffu, lsum1, 2);
    const float inv0 = 1.0f / lsum0, inv1 = 1.0f / lsum1;

    if (lc == 0) {
        g_linv[((size_t)(b * Sq + qg0)) * Hh + h]     = inv0;
        g_linv[((size_t)(b * Sq + qg0 + 8)) * Hh + h] = inv1;
    }

    __half* orow0 = g_ao + (size_t)(b * Sq + qg0) * Dm + h * Dk;
    __half* orow1 = orow0 + 8 * Dm;
#pragma unroll
    for (int nt = 0; nt < 8; nt++) {
        int d = nt * 8 + lc * 2;
        *(__half2*)(orow0 + d) = __floats2half2_rn(o_acc[nt][0] * inv0, o_acc[nt][1] * inv0);
        *(__half2*)(orow1 + d) = __floats2half2_rn(o_acc[nt][2] * inv1, o_acc[nt][3] * inv1);
    }
#undef AT_CPKV
}

// ============================================================================
// K3: normalize: sc[row][:] = fp32(eh[row][:]) * linv[row].
// ============================================================================
__global__ __launch_bounds__(512) void norm_rows(
    float* __restrict__ sc, const __half* __restrict__ eh,
    const float* __restrict__ linv)
{
    const int r = blockIdx.x;
    const float s = linv[r];
    uint2 u = ((const uint2*)(eh + (size_t)r * Sq))[threadIdx.x];
    __half2 h0 = *(__half2*)&u.x;
    __half2 h1 = *(__half2*)&u.y;
    float2 f0 = __half22float2(h0);
    float2 f1 = __half22float2(h1);
    float4 v;
    v.x = f0.x * s; v.y = f0.y * s;
    v.z = f1.x * s; v.w = f1.y * s;
    ((float4*)(sc + (size_t)r * Sq))[threadIdx.x] = v;
}

// ============================================================================
// K4: final projection out = g_ao(f16) @ Wo^T + bo  (R14 proven)
// ============================================================================
__global__ __launch_bounds__(256) void outproj_tc(
    const float* __restrict__ W, const float* __restrict__ bias, float* __restrict__ C)
{
    __shared__ __half As[2][128][24];
    __shared__ __half Bs[2][128][24];
    const int tid = threadIdx.x;
    const int lane = tid & 31, wid = tid >> 5;
    const int wm = wid & 1, wn = wid >> 1;
    const int bm = blockIdx.y * 128, bn = blockIdx.x * 128;
    const int lr = lane >> 2, lc = lane & 3;
    const __half* __restrict__ A = g_ao;

    const int row0 = tid >> 1, seg = (tid & 1) * 8;

    const int a_row = lane & 15;
    const int a_cB  = ((lane >> 4) & 1) * 16;
    const int b_row = (lane & 7) + ((lane >> 3) & 1) * 8;
    const int b_cB  = ((lane >> 4) & 1) * 16;

    const uint32_t sA = s2u(&As[0][0][0]);
    const uint32_t sB = s2u(&Bs[0][0][0]);

    float4 rb0, rb1;

#define OP_CPA(st, k0) \
    cpa16(sA + ((st) * 128 + row0) * 48 + seg * 2, A + (size_t)(bm + row0) * Dm + (k0) + seg)

#define OP_LDB(k0) do { \
    rb0 = *(const float4*)(W + (size_t)(bn + row0) * Dm + (k0) + seg); \
    rb1 = *(const float4*)(W + (size_t)(bn + row0) * Dm + (k0) + seg + 4); \
} while (0)

#define OP_STB(st) do { \
    *(uint4*)&Bs[st][row0][seg] = f8h(rb0, rb1); \
} while (0)

    float acc[4][4][4];
#pragma unroll
    for (int i = 0; i < 4; i++)
#pragma unroll
        for (int j = 0; j < 4; j++)
#pragma unroll
            for (int t = 0; t < 4; t++) acc[i][j][t] = 0.f;

    OP_CPA(0, 0); CP_COMMIT(); OP_LDB(0); OP_STB(0); CP_WAIT0(); __syncthreads();

    for (int it = 0; it < 64; it++) {
        const int cur = it & 1;
        if (it < 63) { OP_CPA(cur ^ 1, (it + 1) * 16); CP_COMMIT(); OP_LDB((it + 1) * 16); }

        uint32_t af[4][4], bf[4][2];
#pragma unroll
        for (int mt = 0; mt < 4; mt++)
            ldsm_x4(af[mt][0], af[mt][1], af[mt][2], af[mt][3],
                sA + (cur * 128 + wm * 64 + mt * 16 + a_row) * 48 + a_cB);
#pragma unroll
        for (int ntp = 0; ntp < 2; ntp++) {
            uint32_t r0, r1, r2, r3;
            ldsm_x4(r0, r1, r2, r3,
                sB + (cur * 128 + wn * 32 + ntp * 16 + b_row) * 48 + b_cB);
            bf[2 * ntp][0] = r0; bf[2 * ntp][1] = r2;
            bf[2 * ntp + 1][0] = r1; bf[2 * ntp + 1][1] = r3;
        }
#pragma unroll
        for (int mt = 0; mt < 4; mt++)
#pragma unroll
            for (int nt = 0; nt < 4; nt++)
                mma_f16(acc[mt][nt], af[mt][0], af[mt][1], af[mt][2], af[mt][3],
                        bf[nt][0], bf[nt][1]);

        if (it < 63) { OP_STB(cur ^ 1); CP_WAIT0(); }
        __syncthreads();
    }

#pragma unroll
    for (int mt = 0; mt < 4; mt++) {
#pragma unroll
        for (int nt = 0; nt < 4; nt++) {
            int col = bn + wn * 32 + nt * 8 + lc * 2;
            float b0 = bias[col], b1 = bias[col + 1];
#pragma unroll
            for (int half = 0; half < 2; half++) {
                int m = bm + wm * 64 + mt * 16 + lr + half * 8;
                float2 v;
                v.x = acc[mt][nt][half * 2 + 0] + b0;
                v.y = acc[mt][nt][half * 2 + 1] + b1;
                *(float2*)(C + (size_t)m * Dm + col) = v;
            }
        }
    }
#undef OP_CPA
#undef OP_LDB
#undef OP_STB
}

// ============================================================================
extern "C" void kernel_launch(void* const* d_in, const int* in_sizes, int n_in,
                              void* d_out, int out_size)
{
    const float* q    = (const float*)d_in[0];
    const float* k    = (const float*)d_in[1];
    const float* v    = (const float*)d_in[2];
    const int*   mask = (const int*)d_in[3];
    const float* Wq   = (const float*)d_in[4];
    const float* bq   = (const float*)d_in[5];
    const float* Wk   = (const float*)d_in[6];
    const float* bk   = (const float*)d_in[7];
    const float* Wv   = (const float*)d_in[8];
    const float* bv   = (const float*)d_in[9];
    const float* Wo   = (const float*)d_in[10];
    const float* bo   = (const float*)d_in[11];

    float* out = (float*)d_out;
    float* sc  = out + (size_t)Bb * Sq * Dm;   // scores_out region

    // one-time resources for the fork-join (host objects, not device memory)
    static cudaStream_t s_side = nullptr;
    static cudaEvent_t  ev_fork = nullptr, ev_join = nullptr;
    if (s_side == nullptr) {
        cudaStreamCreateWithFlags(&s_side, cudaStreamNonBlocking);
        cudaEventCreateWithFlags(&ev_fork, cudaEventDisableTiming);
        cudaEventCreateWithFlags(&ev_join, cudaEventDisableTiming);
    }

    const int attn_smem = 110592;
    cudaFuncSetAttribute(attn_fused, cudaFuncAttributeMaxDynamicSharedMemorySize, attn_smem);

    pack_mask<<<(Bb * Sq * (Sq / 32)) / 256, 256>>>(mask);

    dim3 gp(Dm / 128, (Bb * Sq) / 128, 3);
    proj_tc<<<gp, 256>>>(q, k, v, Wq, Wk, Wv, bq, bk, bv);

    dim3 ga(Sq / QT, Bb * Hh);
    attn_fused<<<ga, 512, attn_smem>>>();

    float* linv_ptr;
    __half* eh_ptr;
    cudaGetSymbolAddress((void**)&linv_ptr, g_linv);
    cudaGetSymbolAddress((void**)&eh_ptr,  g_eh);

    // fork: norm on side stream, outproj on main stream (both depend on attn)
    cudaEventRecord(ev_fork, 0);
    cudaStreamWaitEvent(s_side, ev_fork, 0);

    norm_rows<<<Bb * Sq * Hh, 512, 0, s_side>>>(sc, eh_ptr, linv_ptr);

    dim3 go(Dm / 128, (Bb * Sq) / 128);
    outproj_tc<<<go, 256>>>(Wo, bo, out);

    // join
    cudaEventRecord(ev_join, s_side);
    cudaStreamWaitEvent(0, ev_join, 0);
}